// round 16
// baseline (speedup 1.0000x reference)
#include <cuda_runtime.h>
#include <cuda_fp16.h>
#include <math.h>
#include <stdint.h>

// Problem constants
#define BB 8
#define LL 1024
#define DD 768
#define HH 12
#define HD 64
#define ROWS (BB*LL)   // 8192
#define LOG2E 1.4426950408889634f

// Scratch (device globals: allocation-free rule)
__device__ float  g_tab[HH*4096];         // per-head bias table [12][63*63], pre-scaled by log2e
__device__ __half g_xnh[ROWS*DD];         // fp16 RMSNorm output
__device__ __half g_winh[3*DD*DD];        // fp16 w_in
__device__ __half g_wouth[DD*DD];         // fp16 w_out
__device__ __half g_q[ROWS*DD];           // [B,H,L,HD], fp16, pre-scaled by 0.125*log2e
__device__ __half g_k[ROWS*DD];           // fp16
__device__ __half g_v[ROWS*DD];           // fp16
__device__ __half g_atth[ROWS*DD];        // [B,L,D], fp16 attention output

// ---------------------------------------------------------------------------
// helpers
// ---------------------------------------------------------------------------
__device__ __forceinline__ uint32_t smem_u32(const void* p) {
    uint32_t a;
    asm("{ .reg .u64 t; cvta.to.shared.u64 t, %1; cvt.u32.u64 %0, t; }" : "=r"(a) : "l"(p));
    return a;
}
__device__ __forceinline__ void cpasync16(uint32_t saddr, const void* g) {
    asm volatile("cp.async.cg.shared.global [%0], [%1], 16;" :: "r"(saddr), "l"(g));
}
__device__ __forceinline__ void cp_commit() {
    asm volatile("cp.async.commit_group;" ::: "memory");
}
template<int NN>
__device__ __forceinline__ void cp_wait() {
    asm volatile("cp.async.wait_group %0;" :: "n"(NN) : "memory");
}
__device__ __forceinline__ void mma_f16(float* d, const uint32_t* a, uint32_t b0, uint32_t b1) {
    asm volatile(
        "mma.sync.aligned.m16n8k16.row.col.f32.f16.f16.f32 "
        "{%0,%1,%2,%3}, {%4,%5,%6,%7}, {%8,%9}, {%0,%1,%2,%3};"
        : "+f"(d[0]), "+f"(d[1]), "+f"(d[2]), "+f"(d[3])
        : "r"(a[0]), "r"(a[1]), "r"(a[2]), "r"(a[3]), "r"(b0), "r"(b1));
}
__device__ __forceinline__ void ldm4(uint32_t* f, uint32_t a) {
    asm volatile("ldmatrix.sync.aligned.m8n8.x4.shared.b16 {%0,%1,%2,%3}, [%4];"
                 : "=r"(f[0]), "=r"(f[1]), "=r"(f[2]), "=r"(f[3]) : "r"(a));
}
__device__ __forceinline__ void ldm4t(uint32_t* f, uint32_t a) {
    asm volatile("ldmatrix.sync.aligned.m8n8.x4.trans.shared.b16 {%0,%1,%2,%3}, [%4];"
                 : "=r"(f[0]), "=r"(f[1]), "=r"(f[2]), "=r"(f[3]) : "r"(a));
}
__device__ __forceinline__ float ex2f(float x) {
    float y;
    asm("ex2.approx.f32 %0, %1;" : "=f"(y) : "f"(x));
    return y;
}
// pack two fp32 -> one half2 register (single cvt.rn.f16x2.f32)
__device__ __forceinline__ uint32_t packh2(float lo, float hi) {
    uint32_t y;
    asm("cvt.rn.f16x2.f32 %0, %1, %2;" : "=r"(y) : "f"(hi), "f"(lo));
    return y;
}

// ---------------------------------------------------------------------------
// 1) Fused prologue, one launch:
//    blocks [0,12)            : per-head bias table (x log2e)
//    blocks [12, 12+2304)     : weight f32 -> f16 conversion
//    blocks [2316, 2316+8192) : RMSNorm rows (192 active threads)
// ---------------------------------------------------------------------------
#define WCONV4 ((3*DD*DD + DD*DD) / 4)          // 589824 float4-quads
#define PRE_W  (WCONV4/256)                     // 2304
#define PRO_BLKS (HH + PRE_W + ROWS)            // 10508

__global__ __launch_bounds__(256) void prologue_kernel(const float* __restrict__ bp,
                                                       const float* __restrict__ w_in,
                                                       const float* __restrict__ w_out,
                                                       const float* __restrict__ x,
                                                       const float* __restrict__ wn)
{
    int blk = blockIdx.x;
    int tid = threadIdx.x;
    if (blk < HH) {
        int h = blk;
        float o  = bp[h*6+0];
        float c  = bp[h*6+1];
        float w  = bp[h*6+2];
        float p  = bp[h*6+3];
        float dl = bp[h*6+4];
        float m  = bp[h*6+5];
        float ac = fabsf(c);
        float am = fabsf(m);
        float at = fabsf(tanhf(dl));
        for (int i = tid; i < 63*63; i += 256) {
            int dy = i / 63 - 31;
            int dx = i % 63 - 31;
            float fdy = (float)dy, fdx = (float)dx;
            float theta = atan2f(fdx, fdy);
            float r = sqrtf(fdy*fdy + fdx*fdx + 1e-12f);
            float t1 = powf(fmaxf(r - o, 0.0f), ac);
            float co = cosf((theta - p) * w * 0.5f);
            float t2 = 1.0f - at * powf(co*co, am);
            g_tab[h*4096 + i] = t1 * t2 * LOG2E;      // log2-domain softmax
        }
    } else if (blk < HH + PRE_W) {
        int q = (blk - HH) * 256 + tid;           // quad index
        int i = q * 4;
        const int n1 = 3*DD*DD;
        float4 v;
        __half* dst;
        if (i < n1) {
            v = *(const float4*)(w_in + i);
            dst = g_winh + i;
        } else {
            v = *(const float4*)(w_out + (i - n1));
            dst = g_wouth + (i - n1);
        }
        ((__half2*)dst)[0] = __floats2half2_rn(v.x, v.y);
        ((__half2*)dst)[1] = __floats2half2_rn(v.z, v.w);
    } else {
        int row = blk - (HH + PRE_W);
        __shared__ float ws[6];
        __shared__ float rfac;
        float4 v = make_float4(0.f, 0.f, 0.f, 0.f);
        if (tid < 192) {
            v = *(const float4*)(x + (size_t)row * DD + tid*4);
            float s = v.x*v.x + v.y*v.y + v.z*v.z + v.w*v.w;
#pragma unroll
            for (int o = 16; o; o >>= 1) s += __shfl_xor_sync(0xffffffffu, s, o);
            if ((tid & 31) == 0) ws[tid >> 5] = s;
        }
        __syncthreads();
        if (tid == 0) {
            float t = ws[0] + ws[1] + ws[2] + ws[3] + ws[4] + ws[5];
            rfac = rsqrtf(t * (1.0f/768.0f) + 1e-5f);
        }
        __syncthreads();
        if (tid < 192) {
            float f = rfac;
            float4 w4 = *(const float4*)(wn + tid*4);
            __half* dst = g_xnh + (size_t)row * DD + tid*4;
            ((__half2*)dst)[0] = __floats2half2_rn(v.x*f*w4.x, v.y*f*w4.y);
            ((__half2*)dst)[1] = __floats2half2_rn(v.z*f*w4.z, v.w*f*w4.w);
        }
    }
}

// ---------------------------------------------------------------------------
// 3/5) fp16 m16n8k16 + ldmatrix NT GEMM: C[M,N] = A[M,768]*Bw[N,768]^T + bias
//      CTA 128x128, BK=64 double-buffered cp.async, 8 warps (2x4), warp 64x32.
//      SCATTER=true: half2 scatter into q/k/v (q scaled by 0.125*log2e).
// ---------------------------------------------------------------------------
template<bool SCATTER>
__global__ __launch_bounds__(256) void gemm_h(const __half* __restrict__ A,
                                              const __half* __restrict__ Bw,
                                              const float* __restrict__ bias,
                                              float* __restrict__ Cf,
                                              __half* __restrict__ Qh,
                                              __half* __restrict__ Kh,
                                              __half* __restrict__ Vh,
                                              int N)
{
    extern __shared__ __align__(128) char smc[];
    uint32_t aBase = smem_u32(smc);             // [2][128][64] half, 16KB each
    uint32_t bBase = smem_u32(smc + 32768);     // [2][128][64] half

    int tid = threadIdx.x;
    int wid = tid >> 5, lane = tid & 31;
    int warp_m = wid >> 2, warp_n = wid & 3;    // 2 x 4
    int g = lane >> 2, c = lane & 3;
    int mi = lane >> 3, r = lane & 7;           // ldmatrix lane mapping

    int mBase = blockIdx.y * 128, nBase = blockIdx.x * 128;
    const __half* Agp = A  + (size_t)mBase * DD;
    const __half* Bgp = Bw + (size_t)nBase * DD;

    int srow[4], sch[4];
    uint32_t soff[4];
#pragma unroll
    for (int t = 0; t < 4; t++) {
        int i = tid + t*256;
        srow[t] = i >> 3;
        sch[t]  = i & 7;
        soff[t] = (uint32_t)(srow[t]*128 + ((sch[t] ^ (srow[t] & 7)) << 4));
    }

    float acc[4][4][4];
#pragma unroll
    for (int mt = 0; mt < 4; mt++)
#pragma unroll
        for (int nt = 0; nt < 4; nt++)
#pragma unroll
            for (int k = 0; k < 4; k++) acc[mt][nt][k] = 0.0f;

    const int NT = DD / 64;   // 12

#pragma unroll
    for (int t = 0; t < 4; t++) {
        cpasync16(aBase + soff[t], Agp + (size_t)srow[t]*DD + sch[t]*8);
        cpasync16(bBase + soff[t], Bgp + (size_t)srow[t]*DD + sch[t]*8);
    }
    cp_commit();

    for (int kt = 0; kt < NT; kt++) {
        cp_wait<0>();
        __syncthreads();

        if (kt + 1 < NT) {
            int k0 = (kt + 1) * 64;
            uint32_t bo = (uint32_t)(((kt + 1) & 1) * 16384);
#pragma unroll
            for (int t = 0; t < 4; t++) {
                cpasync16(aBase + bo + soff[t], Agp + (size_t)srow[t]*DD + k0 + sch[t]*8);
                cpasync16(bBase + bo + soff[t], Bgp + (size_t)srow[t]*DD + k0 + sch[t]*8);
            }
            cp_commit();
        }

        uint32_t aB = aBase + (kt & 1) * 16384;
        uint32_t bB = bBase + (kt & 1) * 16384;

#pragma unroll
        for (int ks = 0; ks < 4; ks++) {
            int ch = 2*ks + (mi >> 1);
            uint32_t af[4][4];
#pragma unroll
            for (int mt = 0; mt < 4; mt++) {
                int row = warp_m*64 + mt*16 + (mi & 1)*8 + r;
                ldm4(af[mt], aB + row*128 + ((ch ^ r) << 4));
            }
            uint32_t kr[2][4];
#pragma unroll
            for (int p = 0; p < 2; p++) {
                int row = warp_n*32 + p*16 + (mi & 1)*8 + r;
                ldm4(kr[p], bB + row*128 + ((ch ^ r) << 4));
            }
#pragma unroll
            for (int mt = 0; mt < 4; mt++)
#pragma unroll
                for (int p = 0; p < 2; p++) {
                    mma_f16(acc[mt][2*p],   af[mt], kr[p][0], kr[p][2]);
                    mma_f16(acc[mt][2*p+1], af[mt], kr[p][1], kr[p][3]);
                }
        }
        __syncthreads();
    }

    // epilogue
#pragma unroll
    for (int mt = 0; mt < 4; mt++) {
        int r0 = mBase + warp_m*64 + mt*16 + g;
#pragma unroll
        for (int nt = 0; nt < 4; nt++) {
            int gc = nBase + warp_n*32 + nt*8 + 2*c;
            float bz0 = bias[gc], bz1 = bias[gc+1];
            if (SCATTER) {
                int which = gc / 768;
                int rem = gc - which * 768;
                int h = rem >> 6, hd = rem & 63;
                float sc = (which == 0) ? (0.125f * LOG2E) : 1.0f;   // Q: 1/sqrt(64) * log2e
                __half* dst = (which == 0) ? Qh : (which == 1 ? Kh : Vh);
                __half2 v0 = __floats2half2_rn((acc[mt][nt][0] + bz0)*sc, (acc[mt][nt][1] + bz1)*sc);
                __half2 v1 = __floats2half2_rn((acc[mt][nt][2] + bz0)*sc, (acc[mt][nt][3] + bz1)*sc);
                int b0 = r0 >> 10, l0 = r0 & 1023;
                *(__half2*)&dst[(size_t)((b0*HH + h)*LL + l0)*HD + hd] = v0;
                int r1 = r0 + 8;
                int b1 = r1 >> 10, l1 = r1 & 1023;
                *(__half2*)&dst[(size_t)((b1*HH + h)*LL + l1)*HD + hd] = v1;
            } else {
                float2 v0 = make_float2(acc[mt][nt][0] + bz0, acc[mt][nt][1] + bz1);
                float2 v1 = make_float2(acc[mt][nt][2] + bz0, acc[mt][nt][3] + bz1);
                *(float2*)&Cf[(size_t)r0 * N + gc] = v0;
                *(float2*)&Cf[(size_t)(r0 + 8) * N + gc] = v1;
            }
        }
    }
}

// ---------------------------------------------------------------------------
// 4) Flash attention, fp16 m16n8k16 + ldmatrix. Register-resident P (packed
//    in place), log2-domain softmax, deferred l-reduction, and a 3-stage
//    cp.async K/V pipeline (copies issued two compute phases ahead).
//    Smem: K[3][8KB] | V[3][8KB] | Q[16KB] | tab[15.5KB] = 79.5 KB.
// ---------------------------------------------------------------------------
__global__ __launch_bounds__(256, 2) void attn_h_kernel(__half* __restrict__ out)
{
    extern __shared__ __align__(128) char smc[];
    float* tabs = (float*)(smc + 65536);

    int tid = threadIdx.x;
    int wid = tid >> 5, lane = tid & 31;
    int g = lane >> 2, c = lane & 3;
    int mi = lane >> 3, r = lane & 7;
    int qt = blockIdx.x, bh = blockIdx.y;
    int b = bh / HH, h = bh - b * HH;
    int q0 = qt * 128;

    const __half* qg = g_q + ((size_t)bh * LL + q0) * HD;
    const __half* kg = g_k + (size_t)bh * LL * HD;
    const __half* vg = g_v + (size_t)bh * LL * HD;

    uint32_t kBase = smem_u32(smc);             // 3 x 8192
    uint32_t vBase = smem_u32(smc + 24576);     // 3 x 8192
    uint32_t qB    = smem_u32(smc + 49152);     // 16384

    // Stage Q (128x64 half), swizzled  [group Q]
#pragma unroll
    for (int it = 0; it < 4; it++) {
        int i = tid + it*256;
        int row = i >> 3, ch = i & 7;
        cpasync16(qB + row*128 + ((ch ^ (row & 7)) << 4), qg + row*64 + ch*8);
    }
    cp_commit();
    // Prefetch K/V tiles 0 and 1  [groups 0, 1]
#pragma unroll
    for (int pre = 0; pre < 2; pre++) {
#pragma unroll
        for (int it = 0; it < 2; it++) {
            int i = tid + it*256;
            int row = i >> 3, ch = i & 7;
            uint32_t so = (uint32_t)(pre*8192) + row*128 + ((ch ^ (row & 7)) << 4);
            cpasync16(kBase + so, kg + (size_t)(pre*64 + row)*64 + ch*8);
            cpasync16(vBase + so, vg + (size_t)(pre*64 + row)*64 + ch*8);
        }
        cp_commit();
    }
    for (int i = tid; i < 63*63; i += 256) tabs[i] = g_tab[h*4096 + i];

    cp_wait<2>();          // Q landed (K/V 0,1 may still be in flight)
    __syncthreads();

    uint32_t qf[4][4];
    {
        int rowq = 16*wid + (mi & 1)*8 + r;
#pragma unroll
        for (int ks = 0; ks < 4; ks++) {
            int ch = 2*ks + (mi >> 1);
            ldm4(qf[ks], qB + rowq*128 + ((ch ^ r) << 4));
        }
    }

    int qr0 = q0 + 16*wid + g, qr1 = qr0 + 8;
    const float* ptA = tabs + ((qr0 >> 5) + 31)*63 + (qr0 & 31) + 31 - 2*c;
    const float* ptB = tabs + ((qr1 >> 5) + 31)*63 + (qr1 & 31) + 31 - 2*c;

    float m0 = -1e30f, m1 = -1e30f, l0 = 0.0f, l1 = 0.0f;   // l: per-thread partials
    float o_acc[8][4];
#pragma unroll
    for (int nt = 0; nt < 8; nt++)
#pragma unroll
        for (int k = 0; k < 4; k++) o_acc[nt][k] = 0.0f;

    int stage = 0;           // t % 3
    int pstage = 2;          // (t+2) % 3
    for (int t = 0; t < 16; t++) {
        uint32_t kB = kBase + stage*8192;
        uint32_t vB = vBase + stage*8192;
        cp_wait<1>();        // copy(t) done; copy(t+1) may fly
        __syncthreads();

        if (t + 2 < 16) {
            int kr0 = (t + 2) * 64;
            uint32_t kBn = kBase + pstage*8192;
            uint32_t vBn = vBase + pstage*8192;
#pragma unroll
            for (int it = 0; it < 2; it++) {
                int i = tid + it*256;
                int row = i >> 3, ch = i & 7;
                uint32_t so = row*128 + ((ch ^ (row & 7)) << 4);
                cpasync16(kBn + so, kg + (size_t)(kr0 + row)*64 + ch*8);
                cpasync16(vBn + so, vg + (size_t)(kr0 + row)*64 + ch*8);
            }
        }
        cp_commit();         // empty group near the tail keeps wait<1> exact

        // ---- S = Q K^T (log2-domain) ----
        float s[8][4];
#pragma unroll
        for (int nt = 0; nt < 8; nt++)
#pragma unroll
            for (int k = 0; k < 4; k++) s[nt][k] = 0.0f;

#pragma unroll
        for (int ks = 0; ks < 4; ks++) {
            uint32_t kr[4][4];
#pragma unroll
            for (int p = 0; p < 4; p++) {
                int keyrow = 16*p + (mi & 1)*8 + r;
                int ch = 2*ks + (mi >> 1);
                ldm4(kr[p], kB + keyrow*128 + ((ch ^ r) << 4));
            }
#pragma unroll
            for (int p = 0; p < 4; p++) {
                mma_f16(s[2*p],   qf[ks], kr[p][0], kr[p][2]);
                mma_f16(s[2*p+1], qf[ks], kr[p][1], kr[p][3]);
            }
        }

        // ---- bias + online softmax (base-2); max reduced across 4 lanes ----
        float mx0 = -1e30f, mx1 = -1e30f;
#pragma unroll
        for (int nt = 0; nt < 8; nt++) {
            const int off = (nt < 4) ? (-8*nt) : (32 - 8*nt - 63);
            s[nt][0] += ptA[off];
            s[nt][1] += ptA[off - 1];
            s[nt][2] += ptB[off];
            s[nt][3] += ptB[off - 1];
            mx0 = fmaxf(mx0, fmaxf(s[nt][0], s[nt][1]));
            mx1 = fmaxf(mx1, fmaxf(s[nt][2], s[nt][3]));
        }
        ptA -= 126; ptB -= 126;
        mx0 = fmaxf(mx0, __shfl_xor_sync(0xffffffffu, mx0, 1));
        mx0 = fmaxf(mx0, __shfl_xor_sync(0xffffffffu, mx0, 2));
        mx1 = fmaxf(mx1, __shfl_xor_sync(0xffffffffu, mx1, 1));
        mx1 = fmaxf(mx1, __shfl_xor_sync(0xffffffffu, mx1, 2));

        float mn0 = fmaxf(m0, mx0), mn1 = fmaxf(m1, mx1);
        float sc0 = ex2f(m0 - mn0), sc1 = ex2f(m1 - mn1);
        float rs0 = 0.0f, rs1 = 0.0f;
        // exp + pack P fragments IN PLACE into s[nt][0..1] (s[nt][2..3] die)
#pragma unroll
        for (int nt = 0; nt < 8; nt++) {
            float e0 = ex2f(s[nt][0] - mn0);
            float e1 = ex2f(s[nt][1] - mn0);
            float e2 = ex2f(s[nt][2] - mn1);
            float e3 = ex2f(s[nt][3] - mn1);
            rs0 += e0 + e1;
            rs1 += e2 + e3;
            s[nt][0] = __uint_as_float(packh2(e0, e1));
            s[nt][1] = __uint_as_float(packh2(e2, e3));
        }
        // deferred: per-thread partial l only (cross-lane reduce after loop)
        l0 = l0*sc0 + rs0; m0 = mn0;
        l1 = l1*sc1 + rs1; m1 = mn1;

#pragma unroll
        for (int nt = 0; nt < 8; nt++) {
            o_acc[nt][0] *= sc0; o_acc[nt][1] *= sc0;
            o_acc[nt][2] *= sc1; o_acc[nt][3] *= sc1;
        }

        // ---- O += P V  (P direct from registers: C-frag == A-frag layout) ----
#pragma unroll
        for (int ks = 0; ks < 4; ks++) {
            uint32_t pa[4] = { __float_as_uint(s[2*ks][0]),   __float_as_uint(s[2*ks][1]),
                               __float_as_uint(s[2*ks+1][0]), __float_as_uint(s[2*ks+1][1]) };
            uint32_t vr[4][4];
#pragma unroll
            for (int p = 0; p < 4; p++) {
                int krow = 16*ks + (mi & 1)*8 + r;
                int ch = 2*p + (mi >> 1);
                ldm4t(vr[p], vB + krow*128 + ((ch ^ r) << 4));
            }
#pragma unroll
            for (int p = 0; p < 4; p++) {
                mma_f16(o_acc[2*p],   pa, vr[p][0], vr[p][1]);
                mma_f16(o_acc[2*p+1], pa, vr[p][2], vr[p][3]);
            }
        }

        stage  = (stage  == 2) ? 0 : stage  + 1;
        pstage = (pstage == 2) ? 0 : pstage + 1;
    }

    // finalize l across the 4 lanes sharing each row (valid: m is row-uniform)
    l0 += __shfl_xor_sync(0xffffffffu, l0, 1);
    l0 += __shfl_xor_sync(0xffffffffu, l0, 2);
    l1 += __shfl_xor_sync(0xffffffffu, l1, 1);
    l1 += __shfl_xor_sync(0xffffffffu, l1, 2);

    // normalize + write [B,L,D] fp16 (feeds out-proj A operand)
    float inv0 = 1.0f / l0, inv1 = 1.0f / l1;
    int lr0 = q0 + 16*wid + g, lr1 = lr0 + 8;
#pragma unroll
    for (int nt = 0; nt < 8; nt++) {
        int d = h*HD + nt*8 + 2*c;
        *(__half2*)&out[(size_t)(b*LL + lr0)*DD + d] =
            __floats2half2_rn(o_acc[nt][0]*inv0, o_acc[nt][1]*inv0);
        *(__half2*)&out[(size_t)(b*LL + lr1)*DD + d] =
            __floats2half2_rn(o_acc[nt][2]*inv1, o_acc[nt][3]*inv1);
    }
}

// ---------------------------------------------------------------------------
extern "C" void kernel_launch(void* const* d_in, const int* in_sizes, int n_in,
                              void* d_out, int out_size)
{
    const float* x     = (const float*)d_in[0];
    // d_in[1] = pos (32x32 grid, identical per batch — folded into table indexing)
    const float* wn    = (const float*)d_in[2];
    const float* w_in  = (const float*)d_in[3];
    const float* b_in  = (const float*)d_in[4];
    const float* w_out = (const float*)d_in[5];
    const float* b_out = (const float*)d_in[6];
    const float* bp    = (const float*)d_in[7];
    float* out = (float*)d_out;

    __half *p_xnh, *p_winh, *p_wouth, *p_q, *p_k, *p_v, *p_atth;
    cudaGetSymbolAddress((void**)&p_xnh,   g_xnh);
    cudaGetSymbolAddress((void**)&p_winh,  g_winh);
    cudaGetSymbolAddress((void**)&p_wouth, g_wouth);
    cudaGetSymbolAddress((void**)&p_q,     g_q);
    cudaGetSymbolAddress((void**)&p_k,     g_k);
    cudaGetSymbolAddress((void**)&p_v,     g_v);
    cudaGetSymbolAddress((void**)&p_atth,  g_atth);

    prologue_kernel<<<PRO_BLKS, 256>>>(bp, w_in, w_out, x, wn);

    const int gemm_smem = 65536;
    cudaFuncSetAttribute(gemm_h<true>,  cudaFuncAttributeMaxDynamicSharedMemorySize, gemm_smem);
    cudaFuncSetAttribute(gemm_h<false>, cudaFuncAttributeMaxDynamicSharedMemorySize, gemm_smem);

    gemm_h<true><<<dim3(2304/128, ROWS/128), 256, gemm_smem>>>(
        p_xnh, p_winh, b_in, nullptr, p_q, p_k, p_v, 2304);

    const int attn_smem = 65536 + 63*63*4;    // 81412 B
    cudaFuncSetAttribute(attn_h_kernel, cudaFuncAttributeMaxDynamicSharedMemorySize, attn_smem);
    attn_h_kernel<<<dim3(LL/128, BB*HH), 256, attn_smem>>>(p_atth);

    gemm_h<false><<<dim3(DD/128, ROWS/128), 256, gemm_smem>>>(
        p_atth, p_wouth, b_out, out, nullptr, nullptr, nullptr, DD);
}

// round 17
// speedup vs baseline: 1.5367x; 1.5367x over previous
#include <cuda_runtime.h>
#include <cuda_fp16.h>
#include <math.h>
#include <stdint.h>

// Problem constants
#define BB 8
#define LL 1024
#define DD 768
#define HH 12
#define HD 64
#define ROWS (BB*LL)   // 8192
#define LOG2E 1.4426950408889634f

// Scratch (device globals: allocation-free rule)
__device__ float  g_tab[HH*4096];         // per-head bias table [12][63*63], pre-scaled by log2e
__device__ __half g_xnh[ROWS*DD];         // fp16 RMSNorm output
__device__ __half g_winh[3*DD*DD];        // fp16 w_in
__device__ __half g_wouth[DD*DD];         // fp16 w_out
__device__ __half g_q[ROWS*DD];           // [B,H,L,HD], fp16, pre-scaled by 0.125*log2e
__device__ __half g_k[ROWS*DD];           // fp16
__device__ __half g_v[ROWS*DD];           // fp16
__device__ __half g_atth[ROWS*DD];        // [B,L,D], fp16 attention output

// ---------------------------------------------------------------------------
// helpers
// ---------------------------------------------------------------------------
__device__ __forceinline__ uint32_t smem_u32(const void* p) {
    uint32_t a;
    asm("{ .reg .u64 t; cvta.to.shared.u64 t, %1; cvt.u32.u64 %0, t; }" : "=r"(a) : "l"(p));
    return a;
}
__device__ __forceinline__ void cpasync16(uint32_t saddr, const void* g) {
    asm volatile("cp.async.cg.shared.global [%0], [%1], 16;" :: "r"(saddr), "l"(g));
}
__device__ __forceinline__ void cp_commit() {
    asm volatile("cp.async.commit_group;" ::: "memory");
}
template<int NN>
__device__ __forceinline__ void cp_wait() {
    asm volatile("cp.async.wait_group %0;" :: "n"(NN) : "memory");
}
__device__ __forceinline__ void mma_f16(float* d, const uint32_t* a, uint32_t b0, uint32_t b1) {
    asm volatile(
        "mma.sync.aligned.m16n8k16.row.col.f32.f16.f16.f32 "
        "{%0,%1,%2,%3}, {%4,%5,%6,%7}, {%8,%9}, {%0,%1,%2,%3};"
        : "+f"(d[0]), "+f"(d[1]), "+f"(d[2]), "+f"(d[3])
        : "r"(a[0]), "r"(a[1]), "r"(a[2]), "r"(a[3]), "r"(b0), "r"(b1));
}
__device__ __forceinline__ void ldm4(uint32_t* f, uint32_t a) {
    asm volatile("ldmatrix.sync.aligned.m8n8.x4.shared.b16 {%0,%1,%2,%3}, [%4];"
                 : "=r"(f[0]), "=r"(f[1]), "=r"(f[2]), "=r"(f[3]) : "r"(a));
}
__device__ __forceinline__ void ldm4t(uint32_t* f, uint32_t a) {
    asm volatile("ldmatrix.sync.aligned.m8n8.x4.trans.shared.b16 {%0,%1,%2,%3}, [%4];"
                 : "=r"(f[0]), "=r"(f[1]), "=r"(f[2]), "=r"(f[3]) : "r"(a));
}
__device__ __forceinline__ float ex2f(float x) {
    float y;
    asm("ex2.approx.f32 %0, %1;" : "=f"(y) : "f"(x));
    return y;
}
// pack two fp32 -> one half2 register (single cvt.rn.f16x2.f32)
__device__ __forceinline__ uint32_t packh2(float lo, float hi) {
    uint32_t y;
    asm("cvt.rn.f16x2.f32 %0, %1, %2;" : "=r"(y) : "f"(hi), "f"(lo));
    return y;
}

// ---------------------------------------------------------------------------
// 1) Fused prologue, one launch:
//    blocks [0,12)            : per-head bias table (x log2e)
//    blocks [12, 12+2304)     : weight f32 -> f16 conversion
//    blocks [2316, 2316+8192) : RMSNorm rows (192 active threads)
// ---------------------------------------------------------------------------
#define WCONV4 ((3*DD*DD + DD*DD) / 4)          // 589824 float4-quads
#define PRE_W  (WCONV4/256)                     // 2304
#define PRO_BLKS (HH + PRE_W + ROWS)            // 10508

__global__ __launch_bounds__(256) void prologue_kernel(const float* __restrict__ bp,
                                                       const float* __restrict__ w_in,
                                                       const float* __restrict__ w_out,
                                                       const float* __restrict__ x,
                                                       const float* __restrict__ wn)
{
    int blk = blockIdx.x;
    int tid = threadIdx.x;
    if (blk < HH) {
        int h = blk;
        float o  = bp[h*6+0];
        float c  = bp[h*6+1];
        float w  = bp[h*6+2];
        float p  = bp[h*6+3];
        float dl = bp[h*6+4];
        float m  = bp[h*6+5];
        float ac = fabsf(c);
        float am = fabsf(m);
        float at = fabsf(tanhf(dl));
        for (int i = tid; i < 63*63; i += 256) {
            int dy = i / 63 - 31;
            int dx = i % 63 - 31;
            float fdy = (float)dy, fdx = (float)dx;
            float theta = atan2f(fdx, fdy);
            float r = sqrtf(fdy*fdy + fdx*fdx + 1e-12f);
            float t1 = powf(fmaxf(r - o, 0.0f), ac);
            float co = cosf((theta - p) * w * 0.5f);
            float t2 = 1.0f - at * powf(co*co, am);
            g_tab[h*4096 + i] = t1 * t2 * LOG2E;      // log2-domain softmax
        }
    } else if (blk < HH + PRE_W) {
        int q = (blk - HH) * 256 + tid;           // quad index
        int i = q * 4;
        const int n1 = 3*DD*DD;
        float4 v;
        __half* dst;
        if (i < n1) {
            v = *(const float4*)(w_in + i);
            dst = g_winh + i;
        } else {
            v = *(const float4*)(w_out + (i - n1));
            dst = g_wouth + (i - n1);
        }
        ((__half2*)dst)[0] = __floats2half2_rn(v.x, v.y);
        ((__half2*)dst)[1] = __floats2half2_rn(v.z, v.w);
    } else {
        int row = blk - (HH + PRE_W);
        __shared__ float ws[6];
        __shared__ float rfac;
        float4 v = make_float4(0.f, 0.f, 0.f, 0.f);
        if (tid < 192) {
            v = *(const float4*)(x + (size_t)row * DD + tid*4);
            float s = v.x*v.x + v.y*v.y + v.z*v.z + v.w*v.w;
#pragma unroll
            for (int o = 16; o; o >>= 1) s += __shfl_xor_sync(0xffffffffu, s, o);
            if ((tid & 31) == 0) ws[tid >> 5] = s;
        }
        __syncthreads();
        if (tid == 0) {
            float t = ws[0] + ws[1] + ws[2] + ws[3] + ws[4] + ws[5];
            rfac = rsqrtf(t * (1.0f/768.0f) + 1e-5f);
        }
        __syncthreads();
        if (tid < 192) {
            float f = rfac;
            float4 w4 = *(const float4*)(wn + tid*4);
            __half* dst = g_xnh + (size_t)row * DD + tid*4;
            ((__half2*)dst)[0] = __floats2half2_rn(v.x*f*w4.x, v.y*f*w4.y);
            ((__half2*)dst)[1] = __floats2half2_rn(v.z*f*w4.z, v.w*f*w4.w);
        }
    }
}

// ---------------------------------------------------------------------------
// 3/5) fp16 m16n8k16 + ldmatrix NT GEMM: C[M,N] = A[M,768]*Bw[N,768]^T + bias
//      CTA 128x128, BK=64 double-buffered cp.async, 8 warps (2x4), warp 64x32.
//      SCATTER=true: half2 scatter into q/k/v (q scaled by 0.125*log2e).
// ---------------------------------------------------------------------------
template<bool SCATTER>
__global__ __launch_bounds__(256) void gemm_h(const __half* __restrict__ A,
                                              const __half* __restrict__ Bw,
                                              const float* __restrict__ bias,
                                              float* __restrict__ Cf,
                                              __half* __restrict__ Qh,
                                              __half* __restrict__ Kh,
                                              __half* __restrict__ Vh,
                                              int N)
{
    extern __shared__ __align__(128) char smc[];
    uint32_t aBase = smem_u32(smc);             // [2][128][64] half, 16KB each
    uint32_t bBase = smem_u32(smc + 32768);     // [2][128][64] half

    int tid = threadIdx.x;
    int wid = tid >> 5, lane = tid & 31;
    int warp_m = wid >> 2, warp_n = wid & 3;    // 2 x 4
    int g = lane >> 2, c = lane & 3;
    int mi = lane >> 3, r = lane & 7;           // ldmatrix lane mapping

    int mBase = blockIdx.y * 128, nBase = blockIdx.x * 128;
    const __half* Agp = A  + (size_t)mBase * DD;
    const __half* Bgp = Bw + (size_t)nBase * DD;

    int srow[4], sch[4];
    uint32_t soff[4];
#pragma unroll
    for (int t = 0; t < 4; t++) {
        int i = tid + t*256;
        srow[t] = i >> 3;
        sch[t]  = i & 7;
        soff[t] = (uint32_t)(srow[t]*128 + ((sch[t] ^ (srow[t] & 7)) << 4));
    }

    float acc[4][4][4];
#pragma unroll
    for (int mt = 0; mt < 4; mt++)
#pragma unroll
        for (int nt = 0; nt < 4; nt++)
#pragma unroll
            for (int k = 0; k < 4; k++) acc[mt][nt][k] = 0.0f;

    const int NT = DD / 64;   // 12

#pragma unroll
    for (int t = 0; t < 4; t++) {
        cpasync16(aBase + soff[t], Agp + (size_t)srow[t]*DD + sch[t]*8);
        cpasync16(bBase + soff[t], Bgp + (size_t)srow[t]*DD + sch[t]*8);
    }
    cp_commit();

    for (int kt = 0; kt < NT; kt++) {
        cp_wait<0>();
        __syncthreads();

        if (kt + 1 < NT) {
            int k0 = (kt + 1) * 64;
            uint32_t bo = (uint32_t)(((kt + 1) & 1) * 16384);
#pragma unroll
            for (int t = 0; t < 4; t++) {
                cpasync16(aBase + bo + soff[t], Agp + (size_t)srow[t]*DD + k0 + sch[t]*8);
                cpasync16(bBase + bo + soff[t], Bgp + (size_t)srow[t]*DD + k0 + sch[t]*8);
            }
            cp_commit();
        }

        uint32_t aB = aBase + (kt & 1) * 16384;
        uint32_t bB = bBase + (kt & 1) * 16384;

#pragma unroll
        for (int ks = 0; ks < 4; ks++) {
            int ch = 2*ks + (mi >> 1);
            uint32_t af[4][4];
#pragma unroll
            for (int mt = 0; mt < 4; mt++) {
                int row = warp_m*64 + mt*16 + (mi & 1)*8 + r;
                ldm4(af[mt], aB + row*128 + ((ch ^ r) << 4));
            }
            uint32_t kr[2][4];
#pragma unroll
            for (int p = 0; p < 2; p++) {
                int row = warp_n*32 + p*16 + (mi & 1)*8 + r;
                ldm4(kr[p], bB + row*128 + ((ch ^ r) << 4));
            }
#pragma unroll
            for (int mt = 0; mt < 4; mt++)
#pragma unroll
                for (int p = 0; p < 2; p++) {
                    mma_f16(acc[mt][2*p],   af[mt], kr[p][0], kr[p][2]);
                    mma_f16(acc[mt][2*p+1], af[mt], kr[p][1], kr[p][3]);
                }
        }
        __syncthreads();
    }

    // epilogue
#pragma unroll
    for (int mt = 0; mt < 4; mt++) {
        int r0 = mBase + warp_m*64 + mt*16 + g;
#pragma unroll
        for (int nt = 0; nt < 4; nt++) {
            int gc = nBase + warp_n*32 + nt*8 + 2*c;
            float bz0 = bias[gc], bz1 = bias[gc+1];
            if (SCATTER) {
                int which = gc / 768;
                int rem = gc - which * 768;
                int h = rem >> 6, hd = rem & 63;
                float sc = (which == 0) ? (0.125f * LOG2E) : 1.0f;   // Q: 1/sqrt(64) * log2e
                __half* dst = (which == 0) ? Qh : (which == 1 ? Kh : Vh);
                __half2 v0 = __floats2half2_rn((acc[mt][nt][0] + bz0)*sc, (acc[mt][nt][1] + bz1)*sc);
                __half2 v1 = __floats2half2_rn((acc[mt][nt][2] + bz0)*sc, (acc[mt][nt][3] + bz1)*sc);
                int b0 = r0 >> 10, l0 = r0 & 1023;
                *(__half2*)&dst[(size_t)((b0*HH + h)*LL + l0)*HD + hd] = v0;
                int r1 = r0 + 8;
                int b1 = r1 >> 10, l1 = r1 & 1023;
                *(__half2*)&dst[(size_t)((b1*HH + h)*LL + l1)*HD + hd] = v1;
            } else {
                float2 v0 = make_float2(acc[mt][nt][0] + bz0, acc[mt][nt][1] + bz1);
                float2 v1 = make_float2(acc[mt][nt][2] + bz0, acc[mt][nt][3] + bz1);
                *(float2*)&Cf[(size_t)r0 * N + gc] = v0;
                *(float2*)&Cf[(size_t)(r0 + 8) * N + gc] = v1;
            }
        }
    }
}

// ---------------------------------------------------------------------------
// 4) Flash attention, fp16 m16n8k16 + ldmatrix. Register-resident P (packed
//    in place), log2-domain softmax. l-reduction deferred out of the loop:
//    per-thread partial sums rescaled like O, reduced across lanes once.
// ---------------------------------------------------------------------------
__global__ __launch_bounds__(256, 2) void attn_h_kernel(__half* __restrict__ out)
{
    extern __shared__ __align__(128) char smc[];
    float* tabs = (float*)(smc + 49152);

    int tid = threadIdx.x;
    int wid = tid >> 5, lane = tid & 31;
    int g = lane >> 2, c = lane & 3;
    int mi = lane >> 3, r = lane & 7;
    int qt = blockIdx.x, bh = blockIdx.y;
    int b = bh / HH, h = bh - b * HH;
    int q0 = qt * 128;

    const __half* qg = g_q + ((size_t)bh * LL + q0) * HD;
    const __half* kg = g_k + (size_t)bh * LL * HD;
    const __half* vg = g_v + (size_t)bh * LL * HD;

    uint32_t kBase = smem_u32(smc);
    uint32_t vBase = smem_u32(smc + 16384);
    uint32_t qB    = smem_u32(smc + 32768);

    // Stage Q (128x64 half), swizzled  [group 0]
#pragma unroll
    for (int it = 0; it < 4; it++) {
        int i = tid + it*256;
        int row = i >> 3, ch = i & 7;
        cpasync16(qB + row*128 + ((ch ^ (row & 7)) << 4), qg + row*64 + ch*8);
    }
    cp_commit();
    // Prefetch K/V tile 0  [group 1]
#pragma unroll
    for (int it = 0; it < 2; it++) {
        int i = tid + it*256;
        int row = i >> 3, ch = i & 7;
        uint32_t so = row*128 + ((ch ^ (row & 7)) << 4);
        cpasync16(kBase + so, kg + row*64 + ch*8);
        cpasync16(vBase + so, vg + row*64 + ch*8);
    }
    cp_commit();
    for (int i = tid; i < 63*63; i += 256) tabs[i] = g_tab[h*4096 + i];

    cp_wait<1>();
    __syncthreads();

    uint32_t qf[4][4];
    {
        int rowq = 16*wid + (mi & 1)*8 + r;
#pragma unroll
        for (int ks = 0; ks < 4; ks++) {
            int ch = 2*ks + (mi >> 1);
            ldm4(qf[ks], qB + rowq*128 + ((ch ^ r) << 4));
        }
    }

    int qr0 = q0 + 16*wid + g, qr1 = qr0 + 8;
    const float* ptA = tabs + ((qr0 >> 5) + 31)*63 + (qr0 & 31) + 31 - 2*c;
    const float* ptB = tabs + ((qr1 >> 5) + 31)*63 + (qr1 & 31) + 31 - 2*c;

    float m0 = -1e30f, m1 = -1e30f, l0 = 0.0f, l1 = 0.0f;   // l: per-thread partials
    float o_acc[8][4];
#pragma unroll
    for (int nt = 0; nt < 8; nt++)
#pragma unroll
        for (int k = 0; k < 4; k++) o_acc[nt][k] = 0.0f;

    for (int t = 0; t < 16; t++) {
        uint32_t kB = kBase + (t & 1)*8192;
        uint32_t vB = vBase + (t & 1)*8192;
        cp_wait<0>();
        __syncthreads();

        if (t + 1 < 16) {
            int kr0 = (t + 1) * 64;
            uint32_t kBn = kBase + ((t + 1) & 1)*8192;
            uint32_t vBn = vBase + ((t + 1) & 1)*8192;
#pragma unroll
            for (int it = 0; it < 2; it++) {
                int i = tid + it*256;
                int row = i >> 3, ch = i & 7;
                uint32_t so = row*128 + ((ch ^ (row & 7)) << 4);
                cpasync16(kBn + so, kg + (size_t)(kr0 + row)*64 + ch*8);
                cpasync16(vBn + so, vg + (size_t)(kr0 + row)*64 + ch*8);
            }
            cp_commit();
        }

        // ---- S = Q K^T (log2-domain) ----
        float s[8][4];
#pragma unroll
        for (int nt = 0; nt < 8; nt++)
#pragma unroll
            for (int k = 0; k < 4; k++) s[nt][k] = 0.0f;

#pragma unroll
        for (int ks = 0; ks < 4; ks++) {
            uint32_t kr[4][4];
#pragma unroll
            for (int p = 0; p < 4; p++) {
                int keyrow = 16*p + (mi & 1)*8 + r;
                int ch = 2*ks + (mi >> 1);
                ldm4(kr[p], kB + keyrow*128 + ((ch ^ r) << 4));
            }
#pragma unroll
            for (int p = 0; p < 4; p++) {
                mma_f16(s[2*p],   qf[ks], kr[p][0], kr[p][2]);
                mma_f16(s[2*p+1], qf[ks], kr[p][1], kr[p][3]);
            }
        }

        // ---- bias + online softmax (base-2); max reduced across 4 lanes ----
        float mx0 = -1e30f, mx1 = -1e30f;
#pragma unroll
        for (int nt = 0; nt < 8; nt++) {
            const int off = (nt < 4) ? (-8*nt) : (32 - 8*nt - 63);
            s[nt][0] += ptA[off];
            s[nt][1] += ptA[off - 1];
            s[nt][2] += ptB[off];
            s[nt][3] += ptB[off - 1];
            mx0 = fmaxf(mx0, fmaxf(s[nt][0], s[nt][1]));
            mx1 = fmaxf(mx1, fmaxf(s[nt][2], s[nt][3]));
        }
        ptA -= 126; ptB -= 126;
        mx0 = fmaxf(mx0, __shfl_xor_sync(0xffffffffu, mx0, 1));
        mx0 = fmaxf(mx0, __shfl_xor_sync(0xffffffffu, mx0, 2));
        mx1 = fmaxf(mx1, __shfl_xor_sync(0xffffffffu, mx1, 1));
        mx1 = fmaxf(mx1, __shfl_xor_sync(0xffffffffu, mx1, 2));

        float mn0 = fmaxf(m0, mx0), mn1 = fmaxf(m1, mx1);
        float sc0 = ex2f(m0 - mn0), sc1 = ex2f(m1 - mn1);
        float rs0 = 0.0f, rs1 = 0.0f;
        // exp + pack P fragments IN PLACE into s[nt][0..1] (s[nt][2..3] die)
#pragma unroll
        for (int nt = 0; nt < 8; nt++) {
            float e0 = ex2f(s[nt][0] - mn0);
            float e1 = ex2f(s[nt][1] - mn0);
            float e2 = ex2f(s[nt][2] - mn1);
            float e3 = ex2f(s[nt][3] - mn1);
            rs0 += e0 + e1;
            rs1 += e2 + e3;
            s[nt][0] = __uint_as_float(packh2(e0, e1));
            s[nt][1] = __uint_as_float(packh2(e2, e3));
        }
        // deferred: per-thread partial l only (cross-lane reduce after loop)
        l0 = l0*sc0 + rs0; m0 = mn0;
        l1 = l1*sc1 + rs1; m1 = mn1;

#pragma unroll
        for (int nt = 0; nt < 8; nt++) {
            o_acc[nt][0] *= sc0; o_acc[nt][1] *= sc0;
            o_acc[nt][2] *= sc1; o_acc[nt][3] *= sc1;
        }

        // ---- O += P V  (P direct from registers: C-frag == A-frag layout) ----
#pragma unroll
        for (int ks = 0; ks < 4; ks++) {
            uint32_t pa[4] = { __float_as_uint(s[2*ks][0]),   __float_as_uint(s[2*ks][1]),
                               __float_as_uint(s[2*ks+1][0]), __float_as_uint(s[2*ks+1][1]) };
            uint32_t vr[4][4];
#pragma unroll
            for (int p = 0; p < 4; p++) {
                int krow = 16*ks + (mi & 1)*8 + r;
                int ch = 2*p + (mi >> 1);
                ldm4t(vr[p], vB + krow*128 + ((ch ^ r) << 4));
            }
#pragma unroll
            for (int p = 0; p < 4; p++) {
                mma_f16(o_acc[2*p],   pa, vr[p][0], vr[p][1]);
                mma_f16(o_acc[2*p+1], pa, vr[p][2], vr[p][3]);
            }
        }
    }

    // finalize l across the 4 lanes sharing each row (valid: m is row-uniform)
    l0 += __shfl_xor_sync(0xffffffffu, l0, 1);
    l0 += __shfl_xor_sync(0xffffffffu, l0, 2);
    l1 += __shfl_xor_sync(0xffffffffu, l1, 1);
    l1 += __shfl_xor_sync(0xffffffffu, l1, 2);

    // normalize + write [B,L,D] fp16 (feeds out-proj A operand)
    float inv0 = 1.0f / l0, inv1 = 1.0f / l1;
    int lr0 = q0 + 16*wid + g, lr1 = lr0 + 8;
#pragma unroll
    for (int nt = 0; nt < 8; nt++) {
        int d = h*HD + nt*8 + 2*c;
        *(__half2*)&out[(size_t)(b*LL + lr0)*DD + d] =
            __floats2half2_rn(o_acc[nt][0]*inv0, o_acc[nt][1]*inv0);
        *(__half2*)&out[(size_t)(b*LL + lr1)*DD + d] =
            __floats2half2_rn(o_acc[nt][2]*inv1, o_acc[nt][3]*inv1);
    }
}

// ---------------------------------------------------------------------------
extern "C" void kernel_launch(void* const* d_in, const int* in_sizes, int n_in,
                              void* d_out, int out_size)
{
    const float* x     = (const float*)d_in[0];
    // d_in[1] = pos (32x32 grid, identical per batch — folded into table indexing)
    const float* wn    = (const float*)d_in[2];
    const float* w_in  = (const float*)d_in[3];
    const float* b_in  = (const float*)d_in[4];
    const float* w_out = (const float*)d_in[5];
    const float* b_out = (const float*)d_in[6];
    const float* bp    = (const float*)d_in[7];
    float* out = (float*)d_out;

    __half *p_xnh, *p_winh, *p_wouth, *p_q, *p_k, *p_v, *p_atth;
    cudaGetSymbolAddress((void**)&p_xnh,   g_xnh);
    cudaGetSymbolAddress((void**)&p_winh,  g_winh);
    cudaGetSymbolAddress((void**)&p_wouth, g_wouth);
    cudaGetSymbolAddress((void**)&p_q,     g_q);
    cudaGetSymbolAddress((void**)&p_k,     g_k);
    cudaGetSymbolAddress((void**)&p_v,     g_v);
    cudaGetSymbolAddress((void**)&p_atth,  g_atth);

    prologue_kernel<<<PRO_BLKS, 256>>>(bp, w_in, w_out, x, wn);

    const int gemm_smem = 65536;
    cudaFuncSetAttribute(gemm_h<true>,  cudaFuncAttributeMaxDynamicSharedMemorySize, gemm_smem);
    cudaFuncSetAttribute(gemm_h<false>, cudaFuncAttributeMaxDynamicSharedMemorySize, gemm_smem);

    gemm_h<true><<<dim3(2304/128, ROWS/128), 256, gemm_smem>>>(
        p_xnh, p_winh, b_in, nullptr, p_q, p_k, p_v, 2304);

    const int attn_smem = 49152 + 63*63*4;    // 65028 B
    cudaFuncSetAttribute(attn_h_kernel, cudaFuncAttributeMaxDynamicSharedMemorySize, attn_smem);
    attn_h_kernel<<<dim3(LL/128, BB*HH), 256, attn_smem>>>(p_atth);

    gemm_h<false><<<dim3(DD/128, ROWS/128), 256, gemm_smem>>>(
        p_atth, p_wouth, b_out, out, nullptr, nullptr, nullptr, DD);
}